// round 1
// baseline (speedup 1.0000x reference)
#include <cuda_runtime.h>
#include <math.h>

#define D_DIM 256
#define O_DIM 32
#define NMAX 50000
#define EMAX 800000

// ---------------- scratch (static device globals; no runtime allocation) ---
__device__ float g_B[(size_t)NMAX * D_DIM];   // h1 = A@W+b
__device__ float g_C[(size_t)NMAX * D_DIM];   // nb = h1@Wn+bn
__device__ float g_Y[(size_t)NMAX * D_DIM];   // dinv * nb
__device__ float g_H[(size_t)NMAX * D_DIM];   // layer output
__device__ float g_dinv[NMAX];
__device__ int   g_cnt[NMAX];
__device__ int   g_rowptr[NMAX + 1];
__device__ int   g_cursor[NMAX];
__device__ int   g_colidx[EMAX];

// ---------------- CSR build ------------------------------------------------
__global__ void zero_cnt_kernel(int n) {
    int i = blockIdx.x * blockDim.x + threadIdx.x;
    if (i < n) g_cnt[i] = 0;
}

__global__ void count_edges_kernel(const int* __restrict__ row, int e) {
    int i = blockIdx.x * blockDim.x + threadIdx.x;
    if (i < e) atomicAdd(&g_cnt[row[i]], 1);
}

// single-block chunked Hillis-Steele scan; writes exclusive prefix into
// rowptr[0..n-1] and cursor[0..n-1], total into rowptr[n].
__global__ void scan_kernel(int n) {
    __shared__ int sh[1024];
    __shared__ int carry_sh;
    int t = threadIdx.x;
    if (t == 0) carry_sh = 0;
    __syncthreads();
    for (int base = 0; base < n; base += 1024) {
        int i = base + t;
        int v = (i < n) ? g_cnt[i] : 0;
        sh[t] = v;
        __syncthreads();
        #pragma unroll
        for (int off = 1; off < 1024; off <<= 1) {
            int tmp = (t >= off) ? sh[t - off] : 0;
            __syncthreads();
            sh[t] += tmp;
            __syncthreads();
        }
        int incl = sh[t] + carry_sh;
        int excl = incl - v;
        if (i < n) { g_rowptr[i] = excl; g_cursor[i] = excl; }
        __syncthreads();
        if (t == 1023) carry_sh = incl;
        __syncthreads();
    }
    if (t == 0) g_rowptr[n] = carry_sh;
}

__global__ void fill_csr_kernel(const int* __restrict__ row,
                                const int* __restrict__ col, int e) {
    int i = blockIdx.x * blockDim.x + threadIdx.x;
    if (i < e) {
        int p = atomicAdd(&g_cursor[row[i]], 1);
        g_colidx[p] = col[i];
    }
}

__global__ void dinv_kernel(int n) {
    int i = blockIdx.x * blockDim.x + threadIdx.x;
    if (i < n) g_dinv[i] = rsqrtf((float)(g_cnt[i] + 1));
}

// ---------------- main GEMM: Out[M,256] = A[M,256] @ W[256,256] + bias -----
// optional fused epilogue: Yout[row] = dinv[row] * Out[row]
#define BM 128
#define BN 64
#define BK 16
#define TM 8
#define TN 4

__global__ __launch_bounds__(256)
void gemm_dd_kernel(const float* __restrict__ A, const float* __restrict__ W,
                    const float* __restrict__ bias, float* __restrict__ Out,
                    const float* __restrict__ dinv, float* __restrict__ Yout,
                    int M)
{
    __shared__ __align__(16) float As[BK][BM];
    __shared__ __align__(16) float Bs[BK][BN];
    int tid  = threadIdx.x;
    int brow = blockIdx.x * BM;
    int bcol = blockIdx.y * BN;
    int trow = (tid >> 4) * TM;   // 0..120, step 8
    int tcol = (tid & 15) * TN;   // 0..60,  step 4

    float acc[TM][TN];
    #pragma unroll
    for (int m = 0; m < TM; m++)
        #pragma unroll
        for (int n = 0; n < TN; n++) acc[m][n] = 0.0f;

    for (int k0 = 0; k0 < D_DIM; k0 += BK) {
        // A tile: 128 rows x 16 cols -> 512 float4, 2 per thread (transposed store)
        #pragma unroll
        for (int l = 0; l < 2; l++) {
            int idx = tid + l * 256;
            int r   = idx >> 2;
            int c4  = (idx & 3) * 4;
            int grow = brow + r;
            float4 v = make_float4(0.f, 0.f, 0.f, 0.f);
            if (grow < M)
                v = *reinterpret_cast<const float4*>(A + (size_t)grow * D_DIM + k0 + c4);
            As[c4 + 0][r] = v.x;
            As[c4 + 1][r] = v.y;
            As[c4 + 2][r] = v.z;
            As[c4 + 3][r] = v.w;
        }
        // W tile: 16 rows x 64 cols -> 256 float4, 1 per thread
        {
            int r  = tid >> 4;
            int c4 = (tid & 15) * 4;
            float4 v = *reinterpret_cast<const float4*>(W + (size_t)(k0 + r) * D_DIM + bcol + c4);
            *reinterpret_cast<float4*>(&Bs[r][c4]) = v;
        }
        __syncthreads();

        #pragma unroll
        for (int kk = 0; kk < BK; kk++) {
            float4 a0 = *reinterpret_cast<const float4*>(&As[kk][trow]);
            float4 a1 = *reinterpret_cast<const float4*>(&As[kk][trow + 4]);
            float4 b0 = *reinterpret_cast<const float4*>(&Bs[kk][tcol]);
            float a[TM] = {a0.x, a0.y, a0.z, a0.w, a1.x, a1.y, a1.z, a1.w};
            float b[TN] = {b0.x, b0.y, b0.z, b0.w};
            #pragma unroll
            for (int m = 0; m < TM; m++)
                #pragma unroll
                for (int n = 0; n < TN; n++)
                    acc[m][n] = fmaf(a[m], b[n], acc[m][n]);
        }
        __syncthreads();
    }

    float4 bb = *reinterpret_cast<const float4*>(bias + bcol + tcol);
    #pragma unroll
    for (int m = 0; m < TM; m++) {
        int grow = brow + trow + m;
        if (grow >= M) continue;
        float4 o;
        o.x = acc[m][0] + bb.x;
        o.y = acc[m][1] + bb.y;
        o.z = acc[m][2] + bb.z;
        o.w = acc[m][3] + bb.w;
        *reinterpret_cast<float4*>(Out + (size_t)grow * D_DIM + bcol + tcol) = o;
        if (Yout != nullptr) {
            float di = dinv[grow];
            float4 y;
            y.x = di * o.x; y.y = di * o.y; y.z = di * o.z; y.w = di * o.w;
            *reinterpret_cast<float4*>(Yout + (size_t)grow * D_DIM + bcol + tcol) = y;
        }
    }
}

// ---------------- fused aggregate + APPNP mix + residual + l2norm + relu ---
// one block per node, 256 threads (one per feature dim)
__global__ __launch_bounds__(256)
void agg_combine_kernel(const float* __restrict__ Bm, const float* __restrict__ C,
                        const float* __restrict__ Y, float* __restrict__ H, int M)
{
    int i = blockIdx.x;
    int t = threadIdx.x;
    if (i >= M) return;

    __shared__ int cols[256];
    __shared__ float wsum[8];

    int s = g_rowptr[i];
    int e = g_rowptr[i + 1];
    float acc = 0.0f;
    for (int base = s; base < e; base += 256) {
        int m = min(256, e - base);
        if (t < m) cols[t] = g_colidx[base + t];
        __syncthreads();
        for (int j = 0; j < m; j++)
            acc += Y[(size_t)cols[j] * D_DIM + t];
        __syncthreads();
    }

    float di = g_dinv[i];
    float nb = C[(size_t)i * D_DIM + t];
    float prop = di * acc + di * di * nb;      // agg (neighbors + self loop)
    float h = Bm[(size_t)i * D_DIM + t] + 0.5f * prop + 0.5f * nb;

    // block L2-norm reduction
    float v = h * h;
    #pragma unroll
    for (int o = 16; o > 0; o >>= 1)
        v += __shfl_xor_sync(0xffffffffu, v, o);
    if ((t & 31) == 0) wsum[t >> 5] = v;
    __syncthreads();
    float tot = 0.0f;
    #pragma unroll
    for (int w = 0; w < 8; w++) tot += wsum[w];
    float nrm = sqrtf(tot);
    h = h / fmaxf(nrm, 1e-12f);
    H[(size_t)i * D_DIM + t] = fmaxf(h, 0.0f);   // relu
}

// ---------------- output GEMM: Out[M,32] = H[M,256] @ W2[256,32] + b2 ------
// 32 rows/block, 256 threads, each thread -> 4 output columns
__global__ __launch_bounds__(256)
void gemm_out_kernel(const float* __restrict__ H, const float* __restrict__ W2,
                     const float* __restrict__ b2, float* __restrict__ Out, int M)
{
    extern __shared__ __align__(16) float smem[];
    float* sW = smem;                 // [256][32] row-major (32KB)
    float* sH = smem + D_DIM * 32;    // [32][256]          (32KB)

    int tid  = threadIdx.x;
    int brow = blockIdx.x * 32;

    #pragma unroll
    for (int l = 0; l < 8; l++) {
        int idx = tid + l * 256;      // float4 index, 2048 total
        reinterpret_cast<float4*>(sW)[idx] = reinterpret_cast<const float4*>(W2)[idx];
    }
    #pragma unroll
    for (int l = 0; l < 8; l++) {
        int idx = tid + l * 256;      // float4 index into 32x256
        int r = idx >> 6;
        int c = idx & 63;
        float4 v = make_float4(0.f, 0.f, 0.f, 0.f);
        if (brow + r < M)
            v = reinterpret_cast<const float4*>(H + (size_t)(brow + r) * D_DIM)[c];
        reinterpret_cast<float4*>(sH + r * D_DIM)[c] = v;
    }
    __syncthreads();

    int ry = tid >> 3;            // 0..31 row
    int c4 = (tid & 7) * 4;       // column group
    float4 acc = make_float4(0.f, 0.f, 0.f, 0.f);
    #pragma unroll 8
    for (int k = 0; k < D_DIM; k++) {
        float h = sH[ry * D_DIM + k];
        float4 w = *reinterpret_cast<const float4*>(&sW[k * 32 + c4]);
        acc.x = fmaf(h, w.x, acc.x);
        acc.y = fmaf(h, w.y, acc.y);
        acc.z = fmaf(h, w.z, acc.z);
        acc.w = fmaf(h, w.w, acc.w);
    }
    int grow = brow + ry;
    if (grow < M) {
        float4 bb = *reinterpret_cast<const float4*>(b2 + c4);
        acc.x += bb.x; acc.y += bb.y; acc.z += bb.z; acc.w += bb.w;
        *reinterpret_cast<float4*>(Out + (size_t)grow * O_DIM + c4) = acc;
    }
}

// ---------------- host launcher -------------------------------------------
extern "C" void kernel_launch(void* const* d_in, const int* in_sizes, int n_in,
                              void* d_out, int out_size)
{
    const float* x   = (const float*)d_in[0];
    const int*   ei  = (const int*)  d_in[1];
    const float* W0  = (const float*)d_in[2];
    const float* b0  = (const float*)d_in[3];
    const float* Wn0 = (const float*)d_in[4];
    const float* bn0 = (const float*)d_in[5];
    const float* W1  = (const float*)d_in[6];
    const float* b1  = (const float*)d_in[7];
    const float* Wn1 = (const float*)d_in[8];
    const float* bn1 = (const float*)d_in[9];
    const float* W2  = (const float*)d_in[10];
    const float* b2  = (const float*)d_in[11];

    int M = in_sizes[0] / D_DIM;
    int E = in_sizes[1] / 2;
    const int* erow = ei;
    const int* ecol = ei + E;

    float *pB, *pC, *pY, *pH, *pDinv;
    cudaGetSymbolAddress((void**)&pB,    g_B);
    cudaGetSymbolAddress((void**)&pC,    g_C);
    cudaGetSymbolAddress((void**)&pY,    g_Y);
    cudaGetSymbolAddress((void**)&pH,    g_H);
    cudaGetSymbolAddress((void**)&pDinv, g_dinv);

    int eb = (E + 255) / 256;
    int nb = (M + 255) / 256;

    // CSR build (once per launch; reused by both layers)
    zero_cnt_kernel<<<nb, 256>>>(M);
    count_edges_kernel<<<eb, 256>>>(erow, E);
    scan_kernel<<<1, 1024>>>(M);
    fill_csr_kernel<<<eb, 256>>>(erow, ecol, E);
    dinv_kernel<<<nb, 256>>>(M);

    dim3 gg((M + BM - 1) / BM, D_DIM / BN);

    // layer 1
    gemm_dd_kernel<<<gg, 256>>>(x,  W0,  b0,  pB, nullptr, nullptr, M);
    gemm_dd_kernel<<<gg, 256>>>(pB, Wn0, bn0, pC, pDinv,   pY,      M);
    agg_combine_kernel<<<M, 256>>>(pB, pC, pY, pH, M);

    // layer 2
    gemm_dd_kernel<<<gg, 256>>>(pH, W1,  b1,  pB, nullptr, nullptr, M);
    gemm_dd_kernel<<<gg, 256>>>(pB, Wn1, bn1, pC, pDinv,   pY,      M);
    agg_combine_kernel<<<M, 256>>>(pB, pC, pY, pH, M);

    // output layer
    cudaFuncSetAttribute(gemm_out_kernel,
                         cudaFuncAttributeMaxDynamicSharedMemorySize, 65536);
    gemm_out_kernel<<<(M + 31) / 32, 256, 65536>>>(pH, W2, b2, (float*)d_out, M);
}

// round 3
// speedup vs baseline: 1.3339x; 1.3339x over previous
#include <cuda_runtime.h>
#include <cuda_bf16.h>
#include <math.h>
#include <stdint.h>

#define D_DIM 256
#define O_DIM 32
#define NMAX 50000
#define EMAX 800000

// ---------------- scratch (static device globals; no runtime allocation) ---
__device__ float g_B[(size_t)NMAX * D_DIM];   // h1 = A@W+b
__device__ float g_C[(size_t)NMAX * D_DIM];   // nb  (fused weights)
__device__ float g_Y[(size_t)NMAX * D_DIM];   // dinv * nb
__device__ __nv_bfloat16 g_Ah[(size_t)NMAX * D_DIM];  // GEMM input hi
__device__ __nv_bfloat16 g_Al[(size_t)NMAX * D_DIM];  // GEMM input lo
__device__ __nv_bfloat16 g_Wh[2][512 * 256];  // packed weights [n][k] hi
__device__ __nv_bfloat16 g_Wl[2][512 * 256];  // packed weights [n][k] lo
__device__ float g_biasC[2][512];
__device__ float g_Wf[256 * 256];             // W @ Wn (temp per layer)
__device__ float g_bf[256];                   // b @ Wn + bn (temp per layer)
__device__ float g_dinv[NMAX];
__device__ int   g_cnt[NMAX];
__device__ int   g_rowptr[NMAX + 1];
__device__ int   g_cursor[NMAX];
__device__ int   g_colidx[EMAX];

// ================= helpers =================================================
__device__ __forceinline__ uint32_t smem_u32(const void* p) {
    uint32_t a;
    asm("{ .reg .u64 t; cvta.to.shared.u64 t, %1; cvt.u32.u64 %0, t; }"
        : "=r"(a) : "l"(p));
    return a;
}
__device__ __forceinline__ void ldsm_x4(uint32_t* r, uint32_t addr) {
    asm volatile("ldmatrix.sync.aligned.m8n8.x4.shared.b16 {%0,%1,%2,%3}, [%4];"
                 : "=r"(r[0]), "=r"(r[1]), "=r"(r[2]), "=r"(r[3]) : "r"(addr));
}
__device__ __forceinline__ void mma_bf16(float* c, const uint32_t* a,
                                         uint32_t b0, uint32_t b1) {
    asm volatile(
        "mma.sync.aligned.m16n8k16.row.col.f32.bf16.bf16.f32 "
        "{%0,%1,%2,%3}, {%4,%5,%6,%7}, {%8,%9}, {%0,%1,%2,%3};"
        : "+f"(c[0]), "+f"(c[1]), "+f"(c[2]), "+f"(c[3])
        : "r"(a[0]), "r"(a[1]), "r"(a[2]), "r"(a[3]), "r"(b0), "r"(b1));
}
#define SW128(off) ((off) ^ (((off) >> 3) & 0x70))

// ---------------- CSR build ------------------------------------------------
__global__ void zero_cnt_kernel(int n) {
    int i = blockIdx.x * blockDim.x + threadIdx.x;
    if (i < n) g_cnt[i] = 0;
}
__global__ void count_edges_kernel(const int* __restrict__ row, int e) {
    int i = blockIdx.x * blockDim.x + threadIdx.x;
    if (i < e) atomicAdd(&g_cnt[row[i]], 1);
}
__global__ void scan_kernel(int n) {
    __shared__ int sh[1024];
    __shared__ int carry_sh;
    int t = threadIdx.x;
    if (t == 0) carry_sh = 0;
    __syncthreads();
    for (int base = 0; base < n; base += 1024) {
        int i = base + t;
        int v = (i < n) ? g_cnt[i] : 0;
        sh[t] = v;
        __syncthreads();
        #pragma unroll
        for (int off = 1; off < 1024; off <<= 1) {
            int tmp = (t >= off) ? sh[t - off] : 0;
            __syncthreads();
            sh[t] += tmp;
            __syncthreads();
        }
        int incl = sh[t] + carry_sh;
        int excl = incl - v;
        if (i < n) { g_rowptr[i] = excl; g_cursor[i] = excl; }
        __syncthreads();
        if (t == 1023) carry_sh = incl;
        __syncthreads();
    }
    if (t == 0) g_rowptr[n] = carry_sh;
}
__global__ void fill_csr_kernel(const int* __restrict__ row,
                                const int* __restrict__ col, int e) {
    int i = blockIdx.x * blockDim.x + threadIdx.x;
    if (i < e) {
        int p = atomicAdd(&g_cursor[row[i]], 1);
        g_colidx[p] = col[i];
    }
}
__global__ void dinv_kernel(int n) {
    int i = blockIdx.x * blockDim.x + threadIdx.x;
    if (i < n) g_dinv[i] = rsqrtf((float)(g_cnt[i] + 1));
}

// ---------------- weight prep ---------------------------------------------
__global__ void fuse_w_kernel(const float* __restrict__ W,
                              const float* __restrict__ Wn) {
    int k = blockIdx.x, n = threadIdx.x;
    float acc = 0.0f;
    for (int j = 0; j < 256; j++)
        acc = fmaf(__ldg(W + k * 256 + j), Wn[j * 256 + n], acc);
    g_Wf[k * 256 + n] = acc;
}
__global__ void fuse_b_kernel(const float* __restrict__ b,
                              const float* __restrict__ Wn,
                              const float* __restrict__ bn) {
    int n = threadIdx.x;
    float acc = bn[n];
    for (int j = 0; j < 256; j++)
        acc = fmaf(b[j], Wn[j * 256 + n], acc);
    g_bf[n] = acc;
}
// pack Wcomb[512][256] transposed ([n][k]) + split to bf16 hi/lo; bias vec
__global__ void pack_w_kernel(const float* __restrict__ W,
                              const float* __restrict__ b, int layer) {
    int id = blockIdx.x * 256 + threadIdx.x;   // 512*256 ids
    int n = id >> 8, k = id & 255;
    float w = (n < 256) ? W[k * 256 + n] : g_Wf[k * 256 + (n - 256)];
    __nv_bfloat16 hi = __float2bfloat16(w);
    g_Wh[layer][id] = hi;
    g_Wl[layer][id] = __float2bfloat16(w - __bfloat162float(hi));
    if (k == 0) g_biasC[layer][n] = (n < 256) ? b[n] : g_bf[n - 256];
}
__global__ void split_kernel(const float* __restrict__ x, int total) {
    int i = blockIdx.x * blockDim.x + threadIdx.x;
    if (i < total) {
        float v = x[i];
        __nv_bfloat16 hi = __float2bfloat16(v);
        g_Ah[i] = hi;
        g_Al[i] = __float2bfloat16(v - __bfloat162float(hi));
    }
}

// ---------------- HMMA GEMM: [B|C] = A @ Wcomb, split-bf16 x3 --------------
// grid (ceil(M/128), 4), 256 threads. CTA tile 128x128, BK=64.
// blockIdx.y*128 = column base in combined N=512; cols<256 -> Bout, else Cout+Y
__global__ __launch_bounds__(256, 2)
void hmma_gemm_kernel(const __nv_bfloat16* __restrict__ Ah,
                      const __nv_bfloat16* __restrict__ Al,
                      const __nv_bfloat16* __restrict__ Wh,
                      const __nv_bfloat16* __restrict__ Wl,
                      const float* __restrict__ bias,
                      float* __restrict__ Bout, float* __restrict__ Cout,
                      float* __restrict__ Yout, const float* __restrict__ dinv,
                      int M)
{
    extern __shared__ char dsm_raw[];
    uint32_t dynu = smem_u32(dsm_raw);
    uint32_t pad = ((dynu + 127) & ~127u) - dynu;
    char* base = dsm_raw + pad;
    uint32_t sb = dynu + pad;
    const uint32_t OFF_AH = 0, OFF_AL = 16384, OFF_BH = 32768, OFF_BL = 49152;

    int tid  = threadIdx.x;
    int warp = tid >> 5, lane = tid & 31;
    int brow = blockIdx.x * 128;
    int ncb  = blockIdx.y * 128;            // column base in [0,512)
    int wm   = (warp >> 2) * 64;            // warp row offset in tile
    int wn   = (warp & 3) * 32;             // warp col offset in tile

    float acc[4][4][4];
    #pragma unroll
    for (int mi = 0; mi < 4; mi++)
        #pragma unroll
        for (int ni = 0; ni < 4; ni++)
            #pragma unroll
            for (int q = 0; q < 4; q++) acc[mi][ni][q] = 0.0f;

    for (int chunk = 0; chunk < 4; chunk++) {
        int k0 = chunk * 64;
        // ---- load A tiles (hi & lo): 128 rows x 64 cols bf16, SW128 ----
        #pragma unroll
        for (int l = 0; l < 4; l++) {
            int idx = tid + l * 256;
            int r = idx >> 3, c8 = idx & 7;
            int gr = brow + r;
            uint4 vh = make_uint4(0, 0, 0, 0), vl = make_uint4(0, 0, 0, 0);
            if (gr < M) {
                size_t o = (size_t)gr * 256 + k0 + c8 * 8;
                vh = *(const uint4*)(Ah + o);
                vl = *(const uint4*)(Al + o);
            }
            uint32_t off = (uint32_t)(r * 128 + c8 * 16);
            uint32_t sw = SW128(off);
            *(uint4*)(base + OFF_AH + sw) = vh;
            *(uint4*)(base + OFF_AL + sw) = vl;
        }
        // ---- load W tiles (hi & lo): 128 n-rows x 64 k-cols ----
        #pragma unroll
        for (int l = 0; l < 4; l++) {
            int idx = tid + l * 256;
            int r = idx >> 3, c8 = idx & 7;
            size_t o = (size_t)(ncb + r) * 256 + k0 + c8 * 8;
            uint4 vh = *(const uint4*)(Wh + o);
            uint4 vl = *(const uint4*)(Wl + o);
            uint32_t off = (uint32_t)(r * 128 + c8 * 16);
            uint32_t sw = SW128(off);
            *(uint4*)(base + OFF_BH + sw) = vh;
            *(uint4*)(base + OFF_BL + sw) = vl;
        }
        __syncthreads();

        #pragma unroll
        for (int ks = 0; ks < 4; ks++) {
            // lane-address for ldmatrix.x4 (4 matrices: m/n 0-7,8-15 x k 0-7,8-15)
            uint32_t kb   = (uint32_t)(ks * 32 + ((lane >> 4) & 1) * 16);
            uint32_t kswz = kb ^ ((uint32_t)(lane & 7) << 4);
            uint32_t rsub = (uint32_t)((lane & 7) + ((lane >> 3) & 1) * 8);

            uint32_t adA = sb + (wm + rsub) * 128 + kswz;
            uint32_t adB = sb + (wn + rsub) * 128 + kswz;

            uint32_t a[4][4];                    // reused: hi then lo
            uint32_t bh[2][4], bl[2][4];
            #pragma unroll
            for (int mi = 0; mi < 4; mi++)
                ldsm_x4(a[mi], adA + OFF_AH + mi * 2048);
            #pragma unroll
            for (int nj = 0; nj < 2; nj++) {
                ldsm_x4(bh[nj], adB + OFF_BH + nj * 2048);
                ldsm_x4(bl[nj], adB + OFF_BL + nj * 2048);
            }
            // hh + hl products
            #pragma unroll
            for (int mi = 0; mi < 4; mi++)
                #pragma unroll
                for (int ni = 0; ni < 4; ni++) {
                    int nj = ni >> 1, sel = ni & 1;
                    mma_bf16(acc[mi][ni], a[mi], bh[nj][sel], bh[nj][sel + 2]);
                    mma_bf16(acc[mi][ni], a[mi], bl[nj][sel], bl[nj][sel + 2]);
                }
            // reload A as lo, lh product
            #pragma unroll
            for (int mi = 0; mi < 4; mi++)
                ldsm_x4(a[mi], adA + OFF_AL + mi * 2048);
            #pragma unroll
            for (int mi = 0; mi < 4; mi++)
                #pragma unroll
                for (int ni = 0; ni < 4; ni++) {
                    int nj = ni >> 1, sel = ni & 1;
                    mma_bf16(acc[mi][ni], a[mi], bh[nj][sel], bh[nj][sel + 2]);
                }
        }
        __syncthreads();
    }

    // ---- epilogue: bias add, write B or C(+Y) halves ----
    bool chalf = (ncb >= 256);
    int  cbase = chalf ? (ncb - 256) : ncb;
    #pragma unroll
    for (int mi = 0; mi < 4; mi++) {
        int row0 = brow + wm + mi * 16 + (lane >> 2);
        int row1 = row0 + 8;
        #pragma unroll
        for (int ni = 0; ni < 4; ni++) {
            int gcol = cbase + wn + ni * 8 + (lane & 3) * 2;
            float2 bb = *(const float2*)(bias + (chalf ? 256 : 0) + gcol);
            float2 v0, v1;
            v0.x = acc[mi][ni][0] + bb.x; v0.y = acc[mi][ni][1] + bb.y;
            v1.x = acc[mi][ni][2] + bb.x; v1.y = acc[mi][ni][3] + bb.y;
            if (!chalf) {
                if (row0 < M) *(float2*)(Bout + (size_t)row0 * 256 + gcol) = v0;
                if (row1 < M) *(float2*)(Bout + (size_t)row1 * 256 + gcol) = v1;
            } else {
                if (row0 < M) {
                    float di = dinv[row0];
                    *(float2*)(Cout + (size_t)row0 * 256 + gcol) = v0;
                    float2 y; y.x = di * v0.x; y.y = di * v0.y;
                    *(float2*)(Yout + (size_t)row0 * 256 + gcol) = y;
                }
                if (row1 < M) {
                    float di = dinv[row1];
                    *(float2*)(Cout + (size_t)row1 * 256 + gcol) = v1;
                    float2 y; y.x = di * v1.x; y.y = di * v1.y;
                    *(float2*)(Yout + (size_t)row1 * 256 + gcol) = y;
                }
            }
        }
    }
}

// ---------------- fused aggregate + mix + l2norm + relu -> bf16 hi/lo -----
__global__ __launch_bounds__(256)
void agg_combine_kernel(const float* __restrict__ Bm, const float* __restrict__ C,
                        const float* __restrict__ Y, int M)
{
    int i = blockIdx.x;
    int t = threadIdx.x;
    if (i >= M) return;

    __shared__ int cols[256];
    __shared__ float wsum[8];

    int s = g_rowptr[i];
    int e = g_rowptr[i + 1];
    float acc = 0.0f;
    for (int base = s; base < e; base += 256) {
        int m = min(256, e - base);
        if (t < m) cols[t] = g_colidx[base + t];
        __syncthreads();
        for (int j = 0; j < m; j++)
            acc += Y[(size_t)cols[j] * D_DIM + t];
        __syncthreads();
    }

    float di = g_dinv[i];
    float nb = C[(size_t)i * D_DIM + t];
    float prop = di * acc + di * di * nb;
    float h = Bm[(size_t)i * D_DIM + t] + 0.5f * prop + 0.5f * nb;

    float v = h * h;
    #pragma unroll
    for (int o = 16; o > 0; o >>= 1)
        v += __shfl_xor_sync(0xffffffffu, v, o);
    if ((t & 31) == 0) wsum[t >> 5] = v;
    __syncthreads();
    float tot = 0.0f;
    #pragma unroll
    for (int w = 0; w < 8; w++) tot += wsum[w];
    float nrm = sqrtf(tot);
    h = fmaxf(h / fmaxf(nrm, 1e-12f), 0.0f);

    __nv_bfloat16 hi = __float2bfloat16(h);
    size_t off = (size_t)i * D_DIM + t;
    g_Ah[off] = hi;
    g_Al[off] = __float2bfloat16(h - __bfloat162float(hi));
}

// ---------------- output GEMM: Out[M,32] = (Hh+Hl) @ W2 + b2 --------------
__global__ __launch_bounds__(256)
void gemm_out_kernel(const float* __restrict__ W2,
                     const float* __restrict__ b2, float* __restrict__ Out, int M)
{
    extern __shared__ __align__(16) float smem[];
    float* sW = smem;                 // [256][32] (32KB)
    float* sH = smem + D_DIM * 32;    // [32][256] (32KB)

    int tid  = threadIdx.x;
    int brow = blockIdx.x * 32;

    #pragma unroll
    for (int l = 0; l < 8; l++) {
        int idx = tid + l * 256;
        reinterpret_cast<float4*>(sW)[idx] = reinterpret_cast<const float4*>(W2)[idx];
    }
    #pragma unroll
    for (int l = 0; l < 16; l++) {
        int idx = tid + l * 256;       // bf16x2 index into 32x256 (4096 total)
        int r = idx >> 7, c2 = idx & 127;
        float2 f = make_float2(0.f, 0.f);
        if (brow + r < M) {
            size_t off = (size_t)(brow + r) * D_DIM + c2 * 2;
            __nv_bfloat162 hv = *(const __nv_bfloat162*)(g_Ah + off);
            __nv_bfloat162 lv = *(const __nv_bfloat162*)(g_Al + off);
            f.x = __bfloat162float(hv.x) + __bfloat162float(lv.x);
            f.y = __bfloat162float(hv.y) + __bfloat162float(lv.y);
        }
        *reinterpret_cast<float2*>(sH + r * D_DIM + c2 * 2) = f;
    }
    __syncthreads();

    int ry = tid >> 3;
    int c4 = (tid & 7) * 4;
    float4 acc = make_float4(0.f, 0.f, 0.f, 0.f);
    #pragma unroll 8
    for (int k = 0; k < D_DIM; k++) {
        float h = sH[ry * D_DIM + k];
        float4 w = *reinterpret_cast<const float4*>(&sW[k * 32 + c4]);
        acc.x = fmaf(h, w.x, acc.x);
        acc.y = fmaf(h, w.y, acc.y);
        acc.z = fmaf(h, w.z, acc.z);
        acc.w = fmaf(h, w.w, acc.w);
    }
    int grow = brow + ry;
    if (grow < M) {
        float4 bb = *reinterpret_cast<const float4*>(b2 + c4);
        acc.x += bb.x; acc.y += bb.y; acc.z += bb.z; acc.w += bb.w;
        *reinterpret_cast<float4*>(Out + (size_t)grow * O_DIM + c4) = acc;
    }
}

// ---------------- host launcher -------------------------------------------
extern "C" void kernel_launch(void* const* d_in, const int* in_sizes, int n_in,
                              void* d_out, int out_size)
{
    const float* x   = (const float*)d_in[0];
    const int*   ei  = (const int*)  d_in[1];
    const float* W0  = (const float*)d_in[2];
    const float* b0  = (const float*)d_in[3];
    const float* Wn0 = (const float*)d_in[4];
    const float* bn0 = (const float*)d_in[5];
    const float* W1  = (const float*)d_in[6];
    const float* b1  = (const float*)d_in[7];
    const float* Wn1 = (const float*)d_in[8];
    const float* bn1 = (const float*)d_in[9];
    const float* W2  = (const float*)d_in[10];
    const float* b2  = (const float*)d_in[11];

    int M = in_sizes[0] / D_DIM;
    int E = in_sizes[1] / 2;
    const int* erow = ei;
    const int* ecol = ei + E;

    float *pB, *pC, *pY, *pDinv, *pBiasC;
    __nv_bfloat16 *pAh, *pAl, *pWh, *pWl;
    cudaGetSymbolAddress((void**)&pB,    g_B);
    cudaGetSymbolAddress((void**)&pC,    g_C);
    cudaGetSymbolAddress((void**)&pY,    g_Y);
    cudaGetSymbolAddress((void**)&pDinv, g_dinv);
    cudaGetSymbolAddress((void**)&pAh,   g_Ah);
    cudaGetSymbolAddress((void**)&pAl,   g_Al);
    cudaGetSymbolAddress((void**)&pWh,   g_Wh);
    cudaGetSymbolAddress((void**)&pWl,   g_Wl);
    cudaGetSymbolAddress((void**)&pBiasC, g_biasC);

    int eb = (E + 255) / 256;
    int nb = (M + 255) / 256;

    // CSR build
    zero_cnt_kernel<<<nb, 256>>>(M);
    count_edges_kernel<<<eb, 256>>>(erow, E);
    scan_kernel<<<1, 1024>>>(M);
    fill_csr_kernel<<<eb, 256>>>(erow, ecol, E);
    dinv_kernel<<<nb, 256>>>(M);

    // weight prep (sequential: g_Wf/g_bf reused)
    fuse_w_kernel<<<256, 256>>>(W0, Wn0);
    fuse_b_kernel<<<1, 256>>>(b0, Wn0, bn0);
    pack_w_kernel<<<512, 256>>>(W0, b0, 0);
    fuse_w_kernel<<<256, 256>>>(W1, Wn1);
    fuse_b_kernel<<<1, 256>>>(b1, Wn1, bn1);
    pack_w_kernel<<<512, 256>>>(W1, b1, 1);

    // split input
    split_kernel<<<(M * D_DIM + 255) / 256, 256>>>(x, M * D_DIM);

    static bool attr_done = false;
    if (!attr_done) {
        cudaFuncSetAttribute(hmma_gemm_kernel,
                             cudaFuncAttributeMaxDynamicSharedMemorySize, 65792);
        cudaFuncSetAttribute(gemm_out_kernel,
                             cudaFuncAttributeMaxDynamicSharedMemorySize, 65536);
        attr_done = true;
    }

    dim3 gg((M + 127) / 128, 4);

    // layer 1
    hmma_gemm_kernel<<<gg, 256, 65792>>>(pAh, pAl, pWh, pWl, pBiasC,
                                         pB, pC, pY, pDinv, M);
    agg_combine_kernel<<<M, 256>>>(pB, pC, pY, M);

    // layer 2
    hmma_gemm_kernel<<<gg, 256, 65792>>>(pAh, pAl, pWh + 512 * 256, pWl + 512 * 256,
                                         pBiasC + 512, pB, pC, pY, pDinv, M);
    agg_combine_kernel<<<M, 256>>>(pB, pC, pY, M);

    // output layer
    gemm_out_kernel<<<(M + 31) / 32, 256, 65536>>>(W2, b2, (float*)d_out, M);
}

// round 4
// speedup vs baseline: 1.3541x; 1.0151x over previous
#include <cuda_runtime.h>
#include <cuda_bf16.h>
#include <math.h>
#include <stdint.h>

#define D_DIM 256
#define O_DIM 32
#define NMAX 50000
#define EMAX 800000

// ---------------- scratch (static device globals; no runtime allocation) ---
__device__ float g_B[(size_t)NMAX * D_DIM];   // h1 = A@W+b
__device__ float g_C[(size_t)NMAX * D_DIM];   // nb  (fused weights)
__device__ float g_Y[(size_t)NMAX * D_DIM];   // dinv * nb
__device__ __nv_bfloat16 g_Ah[(size_t)NMAX * D_DIM];  // GEMM input hi
__device__ __nv_bfloat16 g_Al[(size_t)NMAX * D_DIM];  // GEMM input lo
__device__ __nv_bfloat16 g_Wh[2][512 * 256];  // packed weights [n][k] hi
__device__ __nv_bfloat16 g_Wl[2][512 * 256];  // packed weights [n][k] lo
__device__ float g_biasC[2][512];
__device__ float g_Wf[256 * 256];             // W @ Wn (temp per layer)
__device__ float g_bf[256];                   // b @ Wn + bn (temp per layer)
__device__ float g_dinv[NMAX];
__device__ int   g_cnt[NMAX];
__device__ int   g_rowstart[NMAX];
__device__ int   g_cursor[NMAX];
__device__ int   g_colidx[EMAX];
__device__ int   g_base;                      // global slot cursor

// ================= helpers =================================================
__device__ __forceinline__ uint32_t smem_u32(const void* p) {
    uint32_t a;
    asm("{ .reg .u64 t; cvta.to.shared.u64 t, %1; cvt.u32.u64 %0, t; }"
        : "=r"(a) : "l"(p));
    return a;
}
__device__ __forceinline__ void ldsm_x4(uint32_t* r, uint32_t addr) {
    asm volatile("ldmatrix.sync.aligned.m8n8.x4.shared.b16 {%0,%1,%2,%3}, [%4];"
                 : "=r"(r[0]), "=r"(r[1]), "=r"(r[2]), "=r"(r[3]) : "r"(addr));
}
__device__ __forceinline__ void mma_bf16(float* c, const uint32_t* a,
                                         uint32_t b0, uint32_t b1) {
    asm volatile(
        "mma.sync.aligned.m16n8k16.row.col.f32.bf16.bf16.f32 "
        "{%0,%1,%2,%3}, {%4,%5,%6,%7}, {%8,%9}, {%0,%1,%2,%3};"
        : "+f"(c[0]), "+f"(c[1]), "+f"(c[2]), "+f"(c[3])
        : "r"(a[0]), "r"(a[1]), "r"(a[2]), "r"(a[3]), "r"(b0), "r"(b1));
}
__device__ __forceinline__ void cp16(uint32_t s, const void* g, bool p) {
    asm volatile("cp.async.cg.shared.global [%0], [%1], 16, %2;"
                 :: "r"(s), "l"(g), "r"(p ? 16 : 0));
}
#define CP_COMMIT() asm volatile("cp.async.commit_group;" ::: "memory")
#define CP_WAIT(n)  asm volatile("cp.async.wait_group %0;" :: "n"(n) : "memory")
#define SW128(off) ((off) ^ (((off) >> 3) & 0x70))

// ---------------- CSR build (scan-free) ------------------------------------
__global__ void count_edges_kernel(const int* __restrict__ row, int e) {
    int i = blockIdx.x * blockDim.x + threadIdx.x;
    if (i < e) atomicAdd(&g_cnt[row[i]], 1);
}
// warp-aggregated offset assignment (order-free CSR) + dinv
__global__ void offsets_kernel(int n) {
    int i = blockIdx.x * blockDim.x + threadIdx.x;
    int lane = threadIdx.x & 31;
    int c = (i < n) ? g_cnt[i] : 0;
    int incl = c;
    #pragma unroll
    for (int o = 1; o < 32; o <<= 1) {
        int v = __shfl_up_sync(0xffffffffu, incl, o);
        if (lane >= o) incl += v;
    }
    int total = __shfl_sync(0xffffffffu, incl, 31);
    int base = 0;
    if (lane == 31 && total > 0) base = atomicAdd(&g_base, total);
    base = __shfl_sync(0xffffffffu, base, 31);
    if (i < n) {
        int start = base + incl - c;
        g_rowstart[i] = start;
        g_cursor[i]   = start;
        g_dinv[i]     = rsqrtf((float)(c + 1));
    }
}
__global__ void fill_csr_kernel(const int* __restrict__ row,
                                const int* __restrict__ col, int e) {
    int i = blockIdx.x * blockDim.x + threadIdx.x;
    if (i < e) {
        int p = atomicAdd(&g_cursor[row[i]], 1);
        g_colidx[p] = col[i];
    }
}

// ---------------- weight prep ---------------------------------------------
__global__ void fuse_w_kernel(const float* __restrict__ W,
                              const float* __restrict__ Wn) {
    int k = blockIdx.x, n = threadIdx.x;
    float acc = 0.0f;
    for (int j = 0; j < 256; j++)
        acc = fmaf(__ldg(W + k * 256 + j), Wn[j * 256 + n], acc);
    g_Wf[k * 256 + n] = acc;
}
__global__ void fuse_b_kernel(const float* __restrict__ b,
                              const float* __restrict__ Wn,
                              const float* __restrict__ bn) {
    int n = threadIdx.x;
    float acc = bn[n];
    for (int j = 0; j < 256; j++)
        acc = fmaf(b[j], Wn[j * 256 + n], acc);
    g_bf[n] = acc;
}
// pack Wcomb[512][256] transposed ([n][k]) + split to bf16 hi/lo; bias vec
__global__ void pack_w_kernel(const float* __restrict__ W,
                              const float* __restrict__ b, int layer) {
    int id = blockIdx.x * 256 + threadIdx.x;   // 512*256 ids
    int n = id >> 8, k = id & 255;
    float w = (n < 256) ? W[k * 256 + n] : g_Wf[k * 256 + (n - 256)];
    __nv_bfloat16 hi = __float2bfloat16(w);
    g_Wh[layer][id] = hi;
    g_Wl[layer][id] = __float2bfloat16(w - __bfloat162float(hi));
    if (k == 0) g_biasC[layer][n] = (n < 256) ? b[n] : g_bf[n - 256];
}
__global__ void split_kernel(const float* __restrict__ x, int total) {
    int i = blockIdx.x * blockDim.x + threadIdx.x;
    if (i < total) {
        float v = x[i];
        __nv_bfloat16 hi = __float2bfloat16(v);
        g_Ah[i] = hi;
        g_Al[i] = __float2bfloat16(v - __bfloat162float(hi));
    }
}

// ---------------- HMMA GEMM: [B|C] = A @ Wcomb, split-bf16 x3 --------------
// grid (ceil(M/128), 4), 256 threads. CTA tile 128x128, BK=64.
// cp.async double-buffered mainloop (2 stages x 64KB).
#define STAGE_BYTES 65536
__global__ __launch_bounds__(256)
void hmma_gemm_kernel(const __nv_bfloat16* __restrict__ Ah,
                      const __nv_bfloat16* __restrict__ Al,
                      const __nv_bfloat16* __restrict__ Wh,
                      const __nv_bfloat16* __restrict__ Wl,
                      const float* __restrict__ bias,
                      float* __restrict__ Bout, float* __restrict__ Cout,
                      float* __restrict__ Yout, const float* __restrict__ dinv,
                      int M)
{
    extern __shared__ char dsm_raw[];
    uint32_t dynu = smem_u32(dsm_raw);
    uint32_t pad = ((dynu + 127) & ~127u) - dynu;
    uint32_t sb = dynu + pad;
    const uint32_t OFF_AH = 0, OFF_AL = 16384, OFF_BH = 32768, OFF_BL = 49152;

    int tid  = threadIdx.x;
    int warp = tid >> 5, lane = tid & 31;
    int brow = blockIdx.x * 128;
    int ncb  = blockIdx.y * 128;            // column base in [0,512)
    int wm   = (warp >> 2) * 64;            // warp row offset in tile
    int wn   = (warp & 3) * 32;             // warp col offset in tile

    // per-thread load coordinates (4 x 16B per buffer per chunk)
    int lr  = tid >> 3;          // row 0..31 step base
    int lc8 = tid & 7;           // 16B column group

    float acc[4][4][4];
    #pragma unroll
    for (int mi = 0; mi < 4; mi++)
        #pragma unroll
        for (int ni = 0; ni < 4; ni++)
            #pragma unroll
            for (int q = 0; q < 4; q++) acc[mi][ni][q] = 0.0f;

    auto load_chunk = [&](int chunk, int stage) {
        int k0 = chunk * 64;
        uint32_t sbase = sb + stage * STAGE_BYTES;
        #pragma unroll
        for (int l = 0; l < 4; l++) {
            int r = lr + l * 32;
            int gr = brow + r;
            bool p = gr < M;
            uint32_t sw = SW128((uint32_t)(r * 128 + lc8 * 16));
            size_t oa = (size_t)(p ? gr : 0) * 256 + k0 + lc8 * 8;
            cp16(sbase + OFF_AH + sw, Ah + oa, p);
            cp16(sbase + OFF_AL + sw, Al + oa, p);
            size_t ow = (size_t)(ncb + r) * 256 + k0 + lc8 * 8;
            cp16(sbase + OFF_BH + sw, Wh + ow, true);
            cp16(sbase + OFF_BL + sw, Wl + ow, true);
        }
        CP_COMMIT();
    };

    load_chunk(0, 0);

    for (int chunk = 0; chunk < 4; chunk++) {
        int stage = chunk & 1;
        if (chunk < 3) { load_chunk(chunk + 1, stage ^ 1); CP_WAIT(1); }
        else           { CP_WAIT(0); }
        __syncthreads();

        uint32_t sbase = sb + stage * STAGE_BYTES;
        #pragma unroll
        for (int ks = 0; ks < 4; ks++) {
            uint32_t kb   = (uint32_t)(ks * 32 + ((lane >> 4) & 1) * 16);
            uint32_t kswz = kb ^ ((uint32_t)(lane & 7) << 4);
            uint32_t rsub = (uint32_t)((lane & 7) + ((lane >> 3) & 1) * 8);

            uint32_t adA = sbase + (wm + rsub) * 128 + kswz;
            uint32_t adB = sbase + (wn + rsub) * 128 + kswz;

            uint32_t a[4][4];                    // reused: hi then lo
            uint32_t bh[2][4], bl[2][4];
            #pragma unroll
            for (int mi = 0; mi < 4; mi++)
                ldsm_x4(a[mi], adA + OFF_AH + mi * 2048);
            #pragma unroll
            for (int nj = 0; nj < 2; nj++) {
                ldsm_x4(bh[nj], adB + OFF_BH + nj * 2048);
                ldsm_x4(bl[nj], adB + OFF_BL + nj * 2048);
            }
            #pragma unroll
            for (int mi = 0; mi < 4; mi++)
                #pragma unroll
                for (int ni = 0; ni < 4; ni++) {
                    int nj = ni >> 1, sel = ni & 1;
                    mma_bf16(acc[mi][ni], a[mi], bh[nj][sel], bh[nj][sel + 2]);
                    mma_bf16(acc[mi][ni], a[mi], bl[nj][sel], bl[nj][sel + 2]);
                }
            #pragma unroll
            for (int mi = 0; mi < 4; mi++)
                ldsm_x4(a[mi], adA + OFF_AL + mi * 2048);
            #pragma unroll
            for (int mi = 0; mi < 4; mi++)
                #pragma unroll
                for (int ni = 0; ni < 4; ni++) {
                    int nj = ni >> 1, sel = ni & 1;
                    mma_bf16(acc[mi][ni], a[mi], bh[nj][sel], bh[nj][sel + 2]);
                }
        }
        __syncthreads();
    }

    // ---- epilogue: bias add, write B or C(+Y) halves ----
    bool chalf = (ncb >= 256);
    int  cbase = chalf ? (ncb - 256) : ncb;
    #pragma unroll
    for (int mi = 0; mi < 4; mi++) {
        int row0 = brow + wm + mi * 16 + (lane >> 2);
        int row1 = row0 + 8;
        #pragma unroll
        for (int ni = 0; ni < 4; ni++) {
            int gcol = cbase + wn + ni * 8 + (lane & 3) * 2;
            float2 bb = *(const float2*)(bias + (chalf ? 256 : 0) + gcol);
            float2 v0, v1;
            v0.x = acc[mi][ni][0] + bb.x; v0.y = acc[mi][ni][1] + bb.y;
            v1.x = acc[mi][ni][2] + bb.x; v1.y = acc[mi][ni][3] + bb.y;
            if (!chalf) {
                if (row0 < M) *(float2*)(Bout + (size_t)row0 * 256 + gcol) = v0;
                if (row1 < M) *(float2*)(Bout + (size_t)row1 * 256 + gcol) = v1;
            } else {
                if (row0 < M) {
                    float di = dinv[row0];
                    *(float2*)(Cout + (size_t)row0 * 256 + gcol) = v0;
                    float2 y; y.x = di * v0.x; y.y = di * v0.y;
                    *(float2*)(Yout + (size_t)row0 * 256 + gcol) = y;
                }
                if (row1 < M) {
                    float di = dinv[row1];
                    *(float2*)(Cout + (size_t)row1 * 256 + gcol) = v1;
                    float2 y; y.x = di * v1.x; y.y = di * v1.y;
                    *(float2*)(Yout + (size_t)row1 * 256 + gcol) = y;
                }
            }
        }
    }
}

// ---------------- fused aggregate + mix + l2norm + relu -> bf16 hi/lo -----
__global__ __launch_bounds__(256)
void agg_combine_kernel(const float* __restrict__ Bm, const float* __restrict__ C,
                        const float* __restrict__ Y, int M)
{
    int i = blockIdx.x;
    int t = threadIdx.x;
    if (i >= M) return;

    __shared__ int cols[256];
    __shared__ float wsum[8];

    int s = g_rowstart[i];
    int e = s + g_cnt[i];
    float a0 = 0.0f, a1 = 0.0f, a2 = 0.0f, a3 = 0.0f;
    for (int base = s; base < e; base += 256) {
        int m = min(256, e - base);
        if (t < m) cols[t] = g_colidx[base + t];
        __syncthreads();
        int j = 0;
        for (; j + 4 <= m; j += 4) {
            a0 += Y[(size_t)cols[j]     * D_DIM + t];
            a1 += Y[(size_t)cols[j + 1] * D_DIM + t];
            a2 += Y[(size_t)cols[j + 2] * D_DIM + t];
            a3 += Y[(size_t)cols[j + 3] * D_DIM + t];
        }
        for (; j < m; j++)
            a0 += Y[(size_t)cols[j] * D_DIM + t];
        __syncthreads();
    }
    float acc = (a0 + a1) + (a2 + a3);

    float di = g_dinv[i];
    float nb = C[(size_t)i * D_DIM + t];
    float prop = di * acc + di * di * nb;
    float h = Bm[(size_t)i * D_DIM + t] + 0.5f * prop + 0.5f * nb;

    float v = h * h;
    #pragma unroll
    for (int o = 16; o > 0; o >>= 1)
        v += __shfl_xor_sync(0xffffffffu, v, o);
    if ((t & 31) == 0) wsum[t >> 5] = v;
    __syncthreads();
    float tot = 0.0f;
    #pragma unroll
    for (int w = 0; w < 8; w++) tot += wsum[w];
    float nrm = sqrtf(tot);
    h = fmaxf(h / fmaxf(nrm, 1e-12f), 0.0f);

    __nv_bfloat16 hi = __float2bfloat16(h);
    size_t off = (size_t)i * D_DIM + t;
    g_Ah[off] = hi;
    g_Al[off] = __float2bfloat16(h - __bfloat162float(hi));
}

// ---------------- output GEMM: Out[M,32] = (Hh+Hl) @ W2 + b2 --------------
__global__ __launch_bounds__(256)
void gemm_out_kernel(const float* __restrict__ W2,
                     const float* __restrict__ b2, float* __restrict__ Out, int M)
{
    extern __shared__ __align__(16) float smem[];
    float* sW = smem;                 // [256][32] (32KB)
    float* sH = smem + D_DIM * 32;    // [32][256] (32KB)

    int tid  = threadIdx.x;
    int brow = blockIdx.x * 32;

    #pragma unroll
    for (int l = 0; l < 8; l++) {
        int idx = tid + l * 256;
        reinterpret_cast<float4*>(sW)[idx] = reinterpret_cast<const float4*>(W2)[idx];
    }
    #pragma unroll
    for (int l = 0; l < 16; l++) {
        int idx = tid + l * 256;       // bf16x2 index into 32x256 (4096 total)
        int r = idx >> 7, c2 = idx & 127;
        float2 f = make_float2(0.f, 0.f);
        if (brow + r < M) {
            size_t off = (size_t)(brow + r) * D_DIM + c2 * 2;
            __nv_bfloat162 hv = *(const __nv_bfloat162*)(g_Ah + off);
            __nv_bfloat162 lv = *(const __nv_bfloat162*)(g_Al + off);
            f.x = __bfloat162float(hv.x) + __bfloat162float(lv.x);
            f.y = __bfloat162float(hv.y) + __bfloat162float(lv.y);
        }
        *reinterpret_cast<float2*>(sH + r * D_DIM + c2 * 2) = f;
    }
    __syncthreads();

    int ry = tid >> 3;
    int c4 = (tid & 7) * 4;
    float4 acc = make_float4(0.f, 0.f, 0.f, 0.f);
    #pragma unroll 8
    for (int k = 0; k < D_DIM; k++) {
        float h = sH[ry * D_DIM + k];
        float4 w = *reinterpret_cast<const float4*>(&sW[k * 32 + c4]);
        acc.x = fmaf(h, w.x, acc.x);
        acc.y = fmaf(h, w.y, acc.y);
        acc.z = fmaf(h, w.z, acc.z);
        acc.w = fmaf(h, w.w, acc.w);
    }
    int grow = brow + ry;
    if (grow < M) {
        float4 bb = *reinterpret_cast<const float4*>(b2 + c4);
        acc.x += bb.x; acc.y += bb.y; acc.z += bb.z; acc.w += bb.w;
        *reinterpret_cast<float4*>(Out + (size_t)grow * O_DIM + c4) = acc;
    }
}

// ---------------- host launcher -------------------------------------------
extern "C" void kernel_launch(void* const* d_in, const int* in_sizes, int n_in,
                              void* d_out, int out_size)
{
    const float* x   = (const float*)d_in[0];
    const int*   ei  = (const int*)  d_in[1];
    const float* W0  = (const float*)d_in[2];
    const float* b0  = (const float*)d_in[3];
    const float* Wn0 = (const float*)d_in[4];
    const float* bn0 = (const float*)d_in[5];
    const float* W1  = (const float*)d_in[6];
    const float* b1  = (const float*)d_in[7];
    const float* Wn1 = (const float*)d_in[8];
    const float* bn1 = (const float*)d_in[9];
    const float* W2  = (const float*)d_in[10];
    const float* b2  = (const float*)d_in[11];

    int M = in_sizes[0] / D_DIM;
    int E = in_sizes[1] / 2;
    const int* erow = ei;
    const int* ecol = ei + E;

    float *pB, *pC, *pY, *pDinv, *pBiasC;
    __nv_bfloat16 *pAh, *pAl, *pWh, *pWl;
    int *pCnt, *pBase;
    cudaGetSymbolAddress((void**)&pB,    g_B);
    cudaGetSymbolAddress((void**)&pC,    g_C);
    cudaGetSymbolAddress((void**)&pY,    g_Y);
    cudaGetSymbolAddress((void**)&pDinv, g_dinv);
    cudaGetSymbolAddress((void**)&pAh,   g_Ah);
    cudaGetSymbolAddress((void**)&pAl,   g_Al);
    cudaGetSymbolAddress((void**)&pWh,   g_Wh);
    cudaGetSymbolAddress((void**)&pWl,   g_Wl);
    cudaGetSymbolAddress((void**)&pBiasC, g_biasC);
    cudaGetSymbolAddress((void**)&pCnt,  g_cnt);
    cudaGetSymbolAddress((void**)&pBase, g_base);

    int eb = (E + 255) / 256;
    int nb = (M + 255) / 256;

    // CSR build (scan-free)
    cudaMemsetAsync(pCnt, 0, (size_t)M * sizeof(int));
    cudaMemsetAsync(pBase, 0, sizeof(int));
    count_edges_kernel<<<eb, 256>>>(erow, E);
    offsets_kernel<<<nb, 256>>>(M);
    fill_csr_kernel<<<eb, 256>>>(erow, ecol, E);

    // weight prep (sequential: g_Wf/g_bf reused)
    fuse_w_kernel<<<256, 256>>>(W0, Wn0);
    fuse_b_kernel<<<1, 256>>>(b0, Wn0, bn0);
    pack_w_kernel<<<512, 256>>>(W0, b0, 0);
    fuse_w_kernel<<<256, 256>>>(W1, Wn1);
    fuse_b_kernel<<<1, 256>>>(b1, Wn1, bn1);
    pack_w_kernel<<<512, 256>>>(W1, b1, 1);

    // split input
    split_kernel<<<(M * D_DIM + 255) / 256, 256>>>(x, M * D_DIM);

    static bool attr_done = false;
    if (!attr_done) {
        cudaFuncSetAttribute(hmma_gemm_kernel,
                             cudaFuncAttributeMaxDynamicSharedMemorySize,
                             2 * STAGE_BYTES + 256);
        cudaFuncSetAttribute(gemm_out_kernel,
                             cudaFuncAttributeMaxDynamicSharedMemorySize, 65536);
        attr_done = true;
    }

    dim3 gg((M + 127) / 128, 4);

    // layer 1
    hmma_gemm_kernel<<<gg, 256, 2 * STAGE_BYTES + 256>>>(
        pAh, pAl, pWh, pWl, pBiasC, pB, pC, pY, pDinv, M);
    agg_combine_kernel<<<M, 256>>>(pB, pC, pY, M);

    // layer 2
    hmma_gemm_kernel<<<gg, 256, 2 * STAGE_BYTES + 256>>>(
        pAh, pAl, pWh + 512 * 256, pWl + 512 * 256,
        pBiasC + 512, pB, pC, pY, pDinv, M);
    agg_combine_kernel<<<M, 256>>>(pB, pC, pY, M);

    // output layer
    gemm_out_kernel<<<(M + 31) / 32, 256, 65536>>>(W2, b2, (float*)d_out, M);
}